// round 15
// baseline (speedup 1.0000x reference)
#include <cuda_runtime.h>
#include <cuda_bf16.h>
#include <cstdint>

// Problem constants
#define PB   2
#define PS   2048
#define PD   2048
#define PH   16
#define PHKV 4
#define PDH  128
#define PKVD (PHKV * PDH)   // 512
#define PM   (PB * PS)      // 4096
#define NCH  (PD / 16)      // 128 k16-chunks for GEMM

// ---------------------------------------------------------------------------
// Scratch (device globals: no allocations allowed)
// ---------------------------------------------------------------------------
#define A_PLANE_ELEMS  ((size_t)PM * PD)
#define WQ_PLANE_ELEMS ((size_t)PD * PD)
#define WK_PLANE_ELEMS ((size_t)PD * PKVD)
__device__ __align__(128) __nv_bfloat16 g_aq_h[A_PLANE_ELEMS],  g_aq_l[A_PLANE_ELEMS];
__device__ __align__(128) __nv_bfloat16 g_ak_h[A_PLANE_ELEMS],  g_ak_l[A_PLANE_ELEMS];
__device__ __align__(128) __nv_bfloat16 g_av_h[A_PLANE_ELEMS],  g_av_l[A_PLANE_ELEMS];
__device__ __align__(128) __nv_bfloat16 g_ac_h[A_PLANE_ELEMS],  g_ac_l[A_PLANE_ELEMS];
__device__ __align__(128) __nv_bfloat16 g_wq_h[WQ_PLANE_ELEMS], g_wq_l[WQ_PLANE_ELEMS];
__device__ __align__(128) __nv_bfloat16 g_wo_h[WQ_PLANE_ELEMS], g_wo_l[WQ_PLANE_ELEMS];
__device__ __align__(128) __nv_bfloat16 g_wk_h[WK_PLANE_ELEMS], g_wk_l[WK_PLANE_ELEMS];
__device__ __align__(128) __nv_bfloat16 g_wv_h[WK_PLANE_ELEMS], g_wv_l[WK_PLANE_ELEMS];

// Attention packed planes — kt32 tiling (8KB per (b,gkv,kt32) tile)
__device__ __align__(128) __nv_bfloat16 g_qa_h[(size_t)PM * PD],   g_qa_l[(size_t)PM * PD];
__device__ __align__(128) __nv_bfloat16 g_kb_h[(size_t)PM * PKVD], g_kb_l[(size_t)PM * PKVD];
__device__ __align__(128) __nv_bfloat16 g_vb_h[(size_t)PM * PKVD], g_vb_l[(size_t)PM * PKVD];

// Bit-packed mask: 1 bit per (b, s, k)
__device__ __align__(128) uint32_t g_mb[(size_t)PB * PS * PS / 32];   // 1 MB

// ---------------------------------------------------------------------------
// Helpers
// ---------------------------------------------------------------------------
__device__ __forceinline__ uint32_t smem_u32(const void* p) {
    uint32_t a;
    asm("{ .reg .u64 t; cvta.to.shared.u64 t, %1; cvt.u32.u64 %0, t; }"
        : "=r"(a) : "l"(p));
    return a;
}

__device__ __forceinline__ void cp16(uint32_t dst, const void* src) {
    asm volatile("cp.async.cg.shared.global [%0], [%1], 16;"
                 :: "r"(dst), "l"(src) : "memory");
}

__device__ __forceinline__ void mma_bf16(float* c, const uint32_t* a, const uint32_t* b) {
    asm volatile(
        "mma.sync.aligned.m16n8k16.row.col.f32.bf16.bf16.f32 "
        "{%0,%1,%2,%3}, {%4,%5,%6,%7}, {%8,%9}, {%0,%1,%2,%3};"
        : "+f"(c[0]), "+f"(c[1]), "+f"(c[2]), "+f"(c[3])
        : "r"(a[0]), "r"(a[1]), "r"(a[2]), "r"(a[3]),
          "r"(b[0]), "r"(b[1]));
}

__device__ __forceinline__ float ex2f(float x) {
    float r;
    asm("ex2.approx.f32 %0, %1;" : "=f"(r) : "f"(x));
    return r;
}

__device__ __forceinline__ void split2(float f0, float f1, uint32_t& uh, uint32_t& ul) {
    asm("cvt.rn.bf16x2.f32 %0, %1, %2;" : "=r"(uh) : "f"(f1), "f"(f0));
    float h0 = __uint_as_float(uh << 16);
    float h1 = __uint_as_float(uh & 0xFFFF0000u);
    float l0 = f0 - h0, l1 = f1 - h1;
    asm("cvt.rn.bf16x2.f32 %0, %1, %2;" : "=r"(ul) : "f"(l1), "f"(l0));
}

// ---------------------------------------------------------------------------
// pack_mask: int32 mask -> bit mask (warp ballot)
// ---------------------------------------------------------------------------
__global__ void pack_mask(const int* __restrict__ mask, uint32_t* __restrict__ bits)
{
    const int i = blockIdx.x * 256 + threadIdx.x;
    const int v = mask[i];
    const uint32_t b = __ballot_sync(0xffffffffu, v != 0);
    if ((threadIdx.x & 31) == 0) bits[i >> 5] = b;
}

// ---------------------------------------------------------------------------
// pack_a3: q/k/v inputs -> A-fragment hi/lo planes, one launch.
// ---------------------------------------------------------------------------
#define PACKA_BLOCKS_PER 8192   // (PM*PD/4)/256

__global__ void pack_a3(const float* __restrict__ q, const float* __restrict__ k,
                        const float* __restrict__ v,
                        __nv_bfloat16* __restrict__ qhp, __nv_bfloat16* __restrict__ qlp,
                        __nv_bfloat16* __restrict__ khp, __nv_bfloat16* __restrict__ klp,
                        __nv_bfloat16* __restrict__ vhp, __nv_bfloat16* __restrict__ vlp)
{
    const int which = blockIdx.x >> 13;
    const int inner = blockIdx.x & 8191;
    const float* src = (which == 0) ? q : (which == 1) ? k : v;
    __nv_bfloat16* hi = (which == 0) ? qhp : (which == 1) ? khp : vhp;
    __nv_bfloat16* lo = (which == 0) ? qlp : (which == 1) ? klp : vlp;

    int idx = inner * 256 + threadIdx.x;
    int c2 = idx & 1023;
    int mg = idx >> 10;
    int g  = mg & 7;
    int mt = (mg >> 3) & 7;
    int R  = mg >> 6;
    int m  = R * 128 + mt * 16 + g;
    int kcol = c2 * 2;
    int c  = kcol >> 4, kk = kcol & 15;
    int t4 = (kk >> 1) & 3, khi = kk >> 3;

    float2 f0 = ((const float2*)(src + (size_t)m * PD))[c2];
    float2 f1 = ((const float2*)(src + (size_t)(m + 8) * PD))[c2];
    uint32_t uh0, ul0, uh1, ul1;
    split2(f0.x, f0.y, uh0, ul0);
    split2(f1.x, f1.y, uh1, ul1);

    size_t off = (((size_t)R * NCH + c) * 8 + mt) * 512
               + (size_t)(g * 4 + t4) * 16 + khi * 8;
    *(uint2*)((char*)hi + off) = make_uint2(uh0, uh1);
    *(uint2*)((char*)lo + off) = make_uint2(ul0, ul1);
}

// ---------------------------------------------------------------------------
// pack_w4: all four weights -> B-fragment hi/lo planes, one launch.
// ---------------------------------------------------------------------------
__global__ void pack_w4(const float* __restrict__ Wq, const float* __restrict__ Wk,
                        const float* __restrict__ Wv, const float* __restrict__ Wo,
                        __nv_bfloat16* __restrict__ qh, __nv_bfloat16* __restrict__ ql,
                        __nv_bfloat16* __restrict__ kh, __nv_bfloat16* __restrict__ kl,
                        __nv_bfloat16* __restrict__ vh, __nv_bfloat16* __restrict__ vl,
                        __nv_bfloat16* __restrict__ oh, __nv_bfloat16* __restrict__ ol)
{
    __shared__ float t[32][33];
    const int tx = threadIdx.x, ty = threadIdx.y;

    int i = blockIdx.x;
    const float* w; __nv_bfloat16 *hi, *lo; int N, bxn, byk;
    if (i < 4096)      { w = Wq; hi = qh; lo = ql; N = PD;   bxn = i & 63; byk = i >> 6; }
    else if (i < 5120) { i -= 4096; w = Wk; hi = kh; lo = kl; N = PKVD; bxn = i & 15; byk = i >> 4; }
    else if (i < 6144) { i -= 5120; w = Wv; hi = vh; lo = vl; N = PKVD; bxn = i & 15; byk = i >> 4; }
    else               { i -= 6144; w = Wo; hi = oh; lo = ol; N = PD;   bxn = i & 63; byk = i >> 6; }

    const int nx = bxn * 32, k0 = byk * 32;

    #pragma unroll
    for (int j = 0; j < 32; j += 8)
        t[ty + j][tx] = w[(size_t)(k0 + ty + j) * N + nx + tx];
    __syncthreads();

    if (tx < 16) {
        const int k  = k0 + 2 * tx;
        const int c  = k >> 4, kk = k & 15;
        const int t4 = (kk >> 1) & 3, khi = kk >> 3;
        #pragma unroll
        for (int j = 0; j < 32; j += 8) {
            const int n = nx + ty + j;
            uint32_t uh, ul;
            split2(t[2 * tx][ty + j], t[2 * tx + 1][ty + j], uh, ul);
            const int NT = n >> 7, nn = n & 127;
            const int ntile = nn >> 3, g = nn & 7;
            const int lane = g * 4 + t4;
            size_t off = (((size_t)NT * NCH + c) * 16 + ntile) * 256 + lane * 8 + khi * 4;
            *(uint32_t*)((char*)hi + off) = uh;
            *(uint32_t*)((char*)lo + off) = ul;
        }
    }
}

// ---------------------------------------------------------------------------
// GEMM mainloop body (macro) — validated R11/R12
// ---------------------------------------------------------------------------
#define GNSTG      3
#define SUB_BYTES  16384
#define GSTG_BYTES 32768
#define GEMM_SMEM  (GNSTG * GSTG_BYTES)   // 98304

#define GEMM_MAINLOOP()                                                         \
    const uint32_t sbase = smem_u32(dsm);                                       \
    const int t16 = tid * 16;                                                   \
    _Pragma("unroll")                                                           \
    for (int s = 0; s < GNSTG - 1; s++) {                                       \
        _Pragma("unroll")                                                       \
        for (int hf = 0; hf < 2; hf++) {                                        \
            const uint32_t d = sbase + s * GSTG_BYTES + hf * SUB_BYTES + t16;   \
            const size_t o = (size_t)(s * 2 + hf) * 4096 + t16;                 \
            cp16(d,         pAh + o);                                           \
            cp16(d + 4096,  pAl + o);                                           \
            cp16(d + 8192,  pBh + o);                                           \
            cp16(d + 12288, pBl + o);                                           \
        }                                                                       \
        asm volatile("cp.async.commit_group;" ::: "memory");                    \
    }                                                                           \
    _Pragma("unroll")                                                           \
    for (int mt = 0; mt < 4; mt++)                                              \
        _Pragma("unroll")                                                       \
        for (int nt = 0; nt < 4; nt++)                                          \
            _Pragma("unroll")                                                   \
            for (int j = 0; j < 4; j++) acc[mt][nt][j] = 0.0f;                  \
    for (int pc = 0; pc < NCH / 2; pc++) {                                      \
        asm volatile("cp.async.wait_group 1;" ::: "memory");                    \
        __syncthreads();                                                        \
        const int np = pc + GNSTG - 1;                                          \
        if (np < NCH / 2) {                                                     \
            _Pragma("unroll")                                                   \
            for (int hf = 0; hf < 2; hf++) {                                    \
                const uint32_t d = sbase + (np % GNSTG) * GSTG_BYTES            \
                                 + hf * SUB_BYTES + t16;                        \
                const size_t o = (size_t)(np * 2 + hf) * 4096 + t16;            \
                cp16(d,         pAh + o);                                       \
                cp16(d + 4096,  pAl + o);                                       \
                cp16(d + 8192,  pBh + o);                                       \
                cp16(d + 12288, pBl + o);                                       \
            }                                                                   \
        }                                                                       \
        asm volatile("cp.async.commit_group;" ::: "memory");                    \
        _Pragma("unroll")                                                       \
        for (int hf = 0; hf < 2; hf++) {                                        \
            const char* stg = dsm + (pc % GNSTG) * GSTG_BYTES + hf * SUB_BYTES; \
            const uint4* sAh = (const uint4*)(stg);                             \
            const uint4* sAl = (const uint4*)(stg + 4096);                      \
            const uint2* sBh = (const uint2*)(stg + 8192);                      \
            const uint2* sBl = (const uint2*)(stg + 12288);                     \
            uint32_t ahi[4][4], alo[4][4], bfr[4][2];                           \
            _Pragma("unroll")                                                   \
            for (int mt = 0; mt < 4; mt++) {                                    \
                uint4 h = sAh[(warp_m * 4 + mt) * 32 + lane];                   \
                ahi[mt][0] = h.x; ahi[mt][1] = h.y;                             \
                ahi[mt][2] = h.z; ahi[mt][3] = h.w;                             \
                uint4 l = sAl[(warp_m * 4 + mt) * 32 + lane];                   \
                alo[mt][0] = l.x; alo[mt][1] = l.y;                             \
                alo[mt][2] = l.z; alo[mt][3] = l.w;                             \
            }                                                                   \
            _Pragma("unroll")                                                   \
            for (int nt = 0; nt < 4; nt++) {                                    \
                uint2 h = sBh[(warp_n * 4 + nt) * 32 + lane];                   \
                bfr[nt][0] = h.x; bfr[nt][1] = h.y;                             \
            }                                                                   \
            _Pragma("unroll")                                                   \
            for (int mt = 0; mt < 4; mt++)                                      \
                _Pragma("unroll")                                               \
                for (int nt = 0; nt < 4; nt++)                                  \
                    mma_bf16(acc[mt][nt], ahi[mt], bfr[nt]);                    \
            _Pragma("unroll")                                                   \
            for (int mt = 0; mt < 4; mt++)                                      \
                _Pragma("unroll")                                               \
                for (int nt = 0; nt < 4; nt++)                                  \
                    mma_bf16(acc[mt][nt], alo[mt], bfr[nt]);                    \
            _Pragma("unroll")                                                   \
            for (int nt = 0; nt < 4; nt++) {                                    \
                uint2 l = sBl[(warp_n * 4 + nt) * 32 + lane];                   \
                bfr[nt][0] = l.x; bfr[nt][1] = l.y;                             \
            }                                                                   \
            _Pragma("unroll")                                                   \
            for (int mt = 0; mt < 4; mt++)                                      \
                _Pragma("unroll")                                               \
                for (int nt = 0; nt < 4; nt++)                                  \
                    mma_bf16(acc[mt][nt], ahi[mt], bfr[nt]);                    \
        }                                                                       \
    }

// ---------------------------------------------------------------------------
// Merged Q/K/V projection GEMM. K/V epilogues write kt32-tiled planes.
// ---------------------------------------------------------------------------
__global__ __launch_bounds__(256, 2)
void qkv_gemm(const __nv_bfloat16* __restrict__ aqh, const __nv_bfloat16* __restrict__ aql,
              const __nv_bfloat16* __restrict__ akh, const __nv_bfloat16* __restrict__ akl,
              const __nv_bfloat16* __restrict__ avh, const __nv_bfloat16* __restrict__ avl,
              const __nv_bfloat16* __restrict__ wqh, const __nv_bfloat16* __restrict__ wql,
              const __nv_bfloat16* __restrict__ wkh, const __nv_bfloat16* __restrict__ wkl,
              const __nv_bfloat16* __restrict__ wvh, const __nv_bfloat16* __restrict__ wvl,
              __nv_bfloat16* __restrict__ qaPh, __nv_bfloat16* __restrict__ qaPl,
              __nv_bfloat16* __restrict__ kbPh, __nv_bfloat16* __restrict__ kbPl,
              __nv_bfloat16* __restrict__ vbPh, __nv_bfloat16* __restrict__ vbPl)
{
    extern __shared__ char dsm[];
    const int tid  = threadIdx.x;
    const int lane = tid & 31;
    const int wid  = tid >> 5;
    const int warp_m = wid >> 2;
    const int warp_n = wid & 3;
    const int bx = blockIdx.x;
    const int mt0 = blockIdx.y;

    int mode, nt0;
    const __nv_bfloat16 *Ah, *Al, *Bh, *Bl;
    if (bx < 16)      { mode = 1; nt0 = bx;      Ah = aqh; Al = aql; Bh = wqh; Bl = wql; }
    else if (bx < 20) { mode = 2; nt0 = bx - 16; Ah = akh; Al = akl; Bh = wkh; Bl = wkl; }
    else              { mode = 0; nt0 = bx - 20; Ah = avh; Al = avl; Bh = wvh; Bl = wvl; }

    const char* pAh = (const char*)Ah + (size_t)mt0 * NCH * 4096;
    const char* pAl = (const char*)Al + (size_t)mt0 * NCH * 4096;
    const char* pBh = (const char*)Bh + (size_t)nt0 * NCH * 4096;
    const char* pBl = (const char*)Bl + (size_t)nt0 * NCH * 4096;

    float acc[4][4][4];
    GEMM_MAINLOOP();

    const int g  = lane >> 2;
    const int t4 = lane & 3;

    if (mode == 0) {
        // ---- V epilogue: stage fp32 tile to smem, pack to kt32 V B-planes ----
        asm volatile("cp.async.wait_group 0;" ::: "memory");
        __syncthreads();
        float* sC = (float*)dsm;   // [128][129]
        #pragma unroll
        for (int mt = 0; mt < 4; mt++) {
            #pragma unroll
            for (int nt = 0; nt < 4; nt++) {
                const int r = warp_m * 64 + mt * 16 + g;
                const int c = warp_n * 32 + nt * 8 + 2 * t4;
                sC[r * 129 + c]           = acc[mt][nt][0];
                sC[r * 129 + c + 1]       = acc[mt][nt][1];
                sC[(r + 8) * 129 + c]     = acc[mt][nt][2];
                sC[(r + 8) * 129 + c + 1] = acc[mt][nt][3];
            }
        }
        __syncthreads();

        const int gkv = nt0;
        const int b   = mt0 >> 4;
        #pragma unroll
        for (int i = 0; i < 32; i++) {
            const int wI = i * 256 + tid;
            const int d  = wI & 127;
            const int rp = wI >> 7;
            const int sl = rp * 2;
            float f0 = sC[sl * 129 + d];
            float f1 = sC[(sl + 1) * 129 + d];
            uint32_t uh, ul;
            split2(f0, f1, uh, ul);

            const int sin = (mt0 * 128 + sl) & 2047;
            const int t32 = sin >> 5;
            const int kk  = sin & 15;
            const int k16l = (sin >> 4) & 1;
            const int t4v = (kk >> 1) & 3, khiv = kk >> 3;
            const int n8 = d >> 3, gN = d & 7;
            size_t off = ((size_t)(b * PHKV + gkv) * 64 + t32) * 8192
                       + (size_t)n8 * 512
                       + (gN * 4 + t4v) * 16 + k16l * 8 + khiv * 4;
            *(uint32_t*)((char*)vbPh + off) = uh;
            *(uint32_t*)((char*)vbPl + off) = ul;
        }
        return;
    }

    #pragma unroll
    for (int mt = 0; mt < 4; mt++) {
        #pragma unroll
        for (int nt = 0; nt < 4; nt++) {
            const int row0 = mt0 * 128 + warp_m * 64 + mt * 16 + g;
            const int col0 = nt0 * 128 + warp_n * 32 + nt * 8 + 2 * t4;

            if (mode == 1) {
                const float scale = 0.08838834764831845f * 1.4426950408889634f;
                const int bb = row0 >> 11, s = row0 & 2047;
                const int qt = s >> 7, rr = s & 127;
                const int wq_ = rr >> 4;
                const int hh = col0 >> 7, d = col0 & 127;
                const int k16 = d >> 4, khi = (d >> 3) & 1;
                size_t base = (((((size_t)(bb * PH + hh) * 16 + qt) * 8 + wq_) * 8 + k16) * 512)
                            + (size_t)(g * 4 + t4) * 16;
                uint32_t uh0, ul0, uh1, ul1;
                split2(acc[mt][nt][0] * scale, acc[mt][nt][1] * scale, uh0, ul0);
                split2(acc[mt][nt][2] * scale, acc[mt][nt][3] * scale, uh1, ul1);
                *(uint32_t*)((char*)qaPh + base + (2 * khi) * 4)     = uh0;
                *(uint32_t*)((char*)qaPh + base + (1 + 2 * khi) * 4) = uh1;
                *(uint32_t*)((char*)qaPl + base + (2 * khi) * 4)     = ul0;
                *(uint32_t*)((char*)qaPl + base + (1 + 2 * khi) * 4) = ul1;
            } else {
                // K epilogue -> kt32 tiles
                const int bb = row0 >> 11, s = row0 & 2047;
                const int t32 = s >> 5;
                const int n8l = (s & 31) >> 3;
                const int gkv = col0 >> 7, d = col0 & 127;
                const int k16 = d >> 4, khi = (d >> 3) & 1;
                size_t base = ((size_t)(bb * PHKV + gkv) * 64 + t32) * 8192
                            + (size_t)(n8l * 4 + (k16 >> 1)) * 512
                            + (size_t)(g * 4 + t4) * 16 + (k16 & 1) * 8 + khi * 4;
                uint32_t uh0, ul0, uh1, ul1;
                split2(acc[mt][nt][0], acc[mt][nt][1], uh0, ul0);
                split2(acc[mt][nt][2], acc[mt][nt][3], uh1, ul1);
                *(uint32_t*)((char*)kbPh + base)        = uh0;
                *(uint32_t*)((char*)kbPh + base + 2048) = uh1;   // n8l+1
                *(uint32_t*)((char*)kbPl + base)        = ul0;
                *(uint32_t*)((char*)kbPl + base + 2048) = ul1;
            }
        }
    }
}

// ---------------------------------------------------------------------------
// Plain GEMM for O-projection (fp32 C out)
// ---------------------------------------------------------------------------
__global__ __launch_bounds__(256, 2)
void tc_gemm0(const __nv_bfloat16* __restrict__ Ah, const __nv_bfloat16* __restrict__ Al,
              const __nv_bfloat16* __restrict__ Bh, const __nv_bfloat16* __restrict__ Bl,
              float* __restrict__ C, int N)
{
    extern __shared__ char dsm[];
    const int tid  = threadIdx.x;
    const int lane = tid & 31;
    const int wid  = tid >> 5;
    const int warp_m = wid >> 2;
    const int warp_n = wid & 3;
    const int mt0 = blockIdx.y, nt0 = blockIdx.x;

    const char* pAh = (const char*)Ah + (size_t)mt0 * NCH * 4096;
    const char* pAl = (const char*)Al + (size_t)mt0 * NCH * 4096;
    const char* pBh = (const char*)Bh + (size_t)nt0 * NCH * 4096;
    const char* pBl = (const char*)Bl + (size_t)nt0 * NCH * 4096;

    float acc[4][4][4];
    GEMM_MAINLOOP();

    const int g  = lane >> 2;
    const int t4 = lane & 3;
    #pragma unroll
    for (int mt = 0; mt < 4; mt++) {
        #pragma unroll
        for (int nt = 0; nt < 4; nt++) {
            const int row0 = mt0 * 128 + warp_m * 64 + mt * 16 + g;
            const int col0 = nt0 * 128 + warp_n * 32 + nt * 8 + 2 * t4;
            float* Cp = C + (size_t)row0 * N + col0;
            *(float2*)(Cp)                 = make_float2(acc[mt][nt][0], acc[mt][nt][1]);
            *(float2*)(Cp + (size_t)8 * N) = make_float2(acc[mt][nt][2], acc[mt][nt][3]);
        }
    }
}

// ---------------------------------------------------------------------------
// Tensor-core fused GQA flash attention — BK=32, 3-stage 32KB pipeline,
// 2 CTAs/SM. Same total mma/exp counts as BK=64 version.
// ---------------------------------------------------------------------------
#define ATT_STG    32768
#define ATT_SMEM   (3 * ATT_STG)   // 98304

__global__ __launch_bounds__(256, 2)
void gqa_attn_mma(const __nv_bfloat16* __restrict__ Qh, const __nv_bfloat16* __restrict__ Ql,
                  const __nv_bfloat16* __restrict__ Kh, const __nv_bfloat16* __restrict__ Kl,
                  const __nv_bfloat16* __restrict__ Vh, const __nv_bfloat16* __restrict__ Vl,
                  const uint32_t* __restrict__ mbits,
                  __nv_bfloat16* __restrict__ acPh, __nv_bfloat16* __restrict__ acPl)
{
    extern __shared__ char dsm[];
    const int tid  = threadIdx.x;
    const int lane = tid & 31;
    const int w    = tid >> 5;
    const int g    = lane >> 2;
    const int t4   = lane & 3;
    const int qt   = blockIdx.x;
    const int h    = blockIdx.y;
    const int b    = blockIdx.z;
    const int gkv  = h >> 2;

    uint32_t qh[8][4], ql[8][4];
    {
        const size_t qoff = (((((size_t)(b * PH + h) * 16 + qt) * 8 + w) * 8) * 512)
                          + (size_t)lane * 16;
        const char* qb  = (const char*)Qh + qoff;
        const char* qb2 = (const char*)Ql + qoff;
        #pragma unroll
        for (int k16 = 0; k16 < 8; k16++) {
            uint4 v = *(const uint4*)(qb + k16 * 512);
            qh[k16][0] = v.x; qh[k16][1] = v.y; qh[k16][2] = v.z; qh[k16][3] = v.w;
            uint4 u = *(const uint4*)(qb2 + k16 * 512);
            ql[k16][0] = u.x; ql[k16][1] = u.y; ql[k16][2] = u.z; ql[k16][3] = u.w;
        }
    }

    float oacc[16][4];
    #pragma unroll
    for (int n = 0; n < 16; n++)
        #pragma unroll
        for (int j = 0; j < 4; j++) oacc[n][j] = 0.0f;
    float m0 = -3.0e38f, m1 = -3.0e38f, l0 = 0.0f, l1 = 0.0f;

    const size_t kvPlane = ((size_t)(b * PHKV + gkv) * 64);   // 64 kt32 tiles
    const char* pKh = (const char*)Kh + kvPlane * 8192;
    const char* pKl = (const char*)Kl + kvPlane * 8192;
    const char* pVh = (const char*)Vh + kvPlane * 8192;
    const char* pVl = (const char*)Vl + kvPlane * 8192;

    const uint32_t sbase = smem_u32(dsm);
    const int t16 = tid * 16;

    // Prologue: stages 0 and 1 (32KB each: Kh|Kl|Vh|Vl x 8KB)
    #pragma unroll
    for (int s = 0; s < 2; s++) {
        const uint32_t dst = sbase + s * ATT_STG;
        const size_t go = (size_t)s * 8192;
        cp16(dst + t16,          pKh + go + t16);
        cp16(dst + 4096 + t16,   pKh + go + 4096 + t16);
        cp16(dst + 8192 + t16,   pKl + go + t16);
        cp16(dst + 12288 + t16,  pKl + go + 4096 + t16);
        cp16(dst + 16384 + t16,  pVh + go + t16);
        cp16(dst + 20480 + t16,  pVh + go + 4096 + t16);
        cp16(dst + 24576 + t16,  pVl + go + t16);
        cp16(dst + 28672 + t16,  pVl + go + 4096 + t16);
        asm volatile("cp.async.commit_group;" ::: "memory");
    }

    const int r0 = qt * 128 + w * 16 + g;
    const int r1 = r0 + 8;
    const uint32_t* mrow0 = mbits + (size_t)(b * PS + r0) * (PS / 32);
    const uint32_t* mrow1 = mbits + (size_t)(b * PS + r1) * (PS / 32);

    for (int kt = 0; kt < 64; kt++) {
        const uint32_t w0 = mrow0[kt];
        const uint32_t w1 = mrow1[kt];

        asm volatile("cp.async.wait_group 1;" ::: "memory");
        __syncthreads();

        if (kt + 2 < 64) {
            const uint32_t dst = sbase + ((kt + 2) % 3) * ATT_STG;
            const size_t go = (size_t)(kt + 2) * 8192;
            cp16(dst + t16,          pKh + go + t16);
            cp16(dst + 4096 + t16,   pKh + go + 4096 + t16);
            cp16(dst + 8192 + t16,   pKl + go + t16);
            cp16(dst + 12288 + t16,  pKl + go + 4096 + t16);
            cp16(dst + 16384 + t16,  pVh + go + t16);
            cp16(dst + 20480 + t16,  pVh + go + 4096 + t16);
            cp16(dst + 24576 + t16,  pVl + go + t16);
            cp16(dst + 28672 + t16,  pVl + go + 4096 + t16);
        }
        asm volatile("cp.async.commit_group;" ::: "memory");

        const char* stg = dsm + (kt % 3) * ATT_STG;
        const char* sKh = stg;
        const char* sKl = stg + 8192;
        const char* sVh = stg + 16384;
        const char* sVl = stg + 24576;

        // ---- S = Q K^T (3-term), n = 4 kseq-blocks ----
        float sm[4][4];
        #pragma unroll
        for (int n = 0; n < 4; n++)
            #pragma unroll
            for (int j = 0; j < 4; j++) sm[n][j] = 0.0f;

        #pragma unroll
        for (int kp = 0; kp < 4; kp++) {
            uint32_t be[4][2], bo[4][2];
            #pragma unroll
            for (int n = 0; n < 4; n++) {
                uint4 v = *(const uint4*)(sKh + (n * 4 + kp) * 512 + lane * 16);
                be[n][0] = v.x; be[n][1] = v.y; bo[n][0] = v.z; bo[n][1] = v.w;
            }
            #pragma unroll
            for (int n = 0; n < 4; n++) mma_bf16(sm[n], qh[2*kp],   be[n]);
            #pragma unroll
            for (int n = 0; n < 4; n++) mma_bf16(sm[n], qh[2*kp+1], bo[n]);
            #pragma unroll
            for (int n = 0; n < 4; n++) mma_bf16(sm[n], ql[2*kp],   be[n]);
            #pragma unroll
            for (int n = 0; n < 4; n++) mma_bf16(sm[n], ql[2*kp+1], bo[n]);
            #pragma unroll
            for (int n = 0; n < 4; n++) {
                uint4 u = *(const uint4*)(sKl + (n * 4 + kp) * 512 + lane * 16);
                be[n][0] = u.x; be[n][1] = u.y; bo[n][0] = u.z; bo[n][1] = u.w;
            }
            #pragma unroll
            for (int n = 0; n < 4; n++) mma_bf16(sm[n], qh[2*kp],   be[n]);
            #pragma unroll
            for (int n = 0; n < 4; n++) mma_bf16(sm[n], qh[2*kp+1], bo[n]);
        }

        // ---- bit-mask + online softmax (base-2) ----
        float mx0 = -3.0e38f, mx1 = -3.0e38f;
        #pragma unroll
        for (int n = 0; n < 4; n++) {
            const int sh = 2 * t4 + 8 * n;
            if (!((w0 >> sh) & 1u))       sm[n][0] = -1e9f;
            if (!((w0 >> (sh + 1)) & 1u)) sm[n][1] = -1e9f;
            if (!((w1 >> sh) & 1u))       sm[n][2] = -1e9f;
            if (!((w1 >> (sh + 1)) & 1u)) sm[n][3] = -1e9f;
            mx0 = fmaxf(mx0, fmaxf(sm[n][0], sm[n][1]));
            mx1 = fmaxf(mx1, fmaxf(sm[n][2], sm[n][3]));
        }
        #pragma unroll
        for (int off = 1; off <= 2; off <<= 1) {
            mx0 = fmaxf(mx0, __shfl_xor_sync(0xffffffffu, mx0, off, 4));
            mx1 = fmaxf(mx1, __shfl_xor_sync(0xffffffffu, mx1, off, 4));
        }
        const float mn0 = fmaxf(m0, mx0);
        const float mn1 = fmaxf(m1, mx1);
        const float a0 = ex2f(m0 - mn0);
        const float a1 = ex2f(m1 - mn1);
        m0 = mn0; m1 = mn1;

        float rs0 = 0.0f, rs1 = 0.0f;
        #pragma unroll
        for (int n = 0; n < 4; n++) {
            sm[n][0] = ex2f(sm[n][0] - m0); rs0 += sm[n][0];
            sm[n][1] = ex2f(sm[n][1] - m0); rs0 += sm[n][1];
            sm[n][2] = ex2f(sm[n][2] - m1); rs1 += sm[n][2];
            sm[n][3] = ex2f(sm[n][3] - m1); rs1 += sm[n][3];
        }
        #pragma unroll
        for (int off = 1; off <= 2; off <<= 1) {
            rs0 += __shfl_xor_sync(0xffffffffu, rs0, off, 4);
            rs1 += __shfl_xor_sync(0xffffffffu, rs1, off, 4);
        }
        l0 = l0 * a0 + rs0;
        l1 = l1 * a1 + rs1;

        if (__any_sync(0xffffffffu, (a0 != 1.0f) || (a1 != 1.0f))) {
            #pragma unroll
            for (int n = 0; n < 16; n++) {
                oacc[n][0] *= a0; oacc[n][1] *= a0;
                oacc[n][2] *= a1; oacc[n][3] *= a1;
            }
        }

        // ---- O += P V (3-term); P: k16 pair {0,1} = sm[0..1], sm[2..3] ----
        {
            uint32_t phe[4], ple[4], pho[4], plo[4];
            split2(sm[0][0], sm[0][1], phe[0], ple[0]);
            split2(sm[0][2], sm[0][3], phe[1], ple[1]);
            split2(sm[1][0], sm[1][1], phe[2], ple[2]);
            split2(sm[1][2], sm[1][3], phe[3], ple[3]);
            split2(sm[2][0], sm[2][1], pho[0], plo[0]);
            split2(sm[2][2], sm[2][3], pho[1], plo[1]);
            split2(sm[3][0], sm[3][1], pho[2], plo[2]);
            split2(sm[3][2], sm[3][3], pho[3], plo[3]);

            #pragma unroll
            for (int ng = 0; ng < 4; ng++) {
                uint32_t ve[4][2], vo[4][2];
                #pragma unroll
                for (int j = 0; j < 4; j++) {
                    uint4 v = *(const uint4*)(sVh + (ng * 4 + j) * 512 + lane * 16);
                    ve[j][0] = v.x; ve[j][1] = v.y; vo[j][0] = v.z; vo[j][1] = v.w;
                }
                #pragma unroll
                for (int j = 0; j < 4; j++) mma_bf16(oacc[ng*4 + j], phe, ve[j]);
                #pragma unroll
                for (int j = 0; j < 4; j++) mma_bf16(oacc[ng*4 + j], pho, vo[j]);
                #pragma unroll
                for (int j = 0; j < 4; j++) mma_bf16(oacc[ng*4 + j], ple, ve[j]);
                #pragma unroll
                for (int j = 0; j < 4; j++) mma_bf16(oacc[ng*4 + j], plo, vo[j]);
            }
            #pragma unroll
            for (int ng = 0; ng < 4; ng++) {
                uint32_t ue[4][2], uo[4][2];
                #pragma unroll
                for (int j = 0; j < 4; j++) {
                    uint4 u = *(const uint4*)(sVl + (ng * 4 + j) * 512 + lane * 16);
                    ue[j][0] = u.x; ue[j][1] = u.y; uo[j][0] = u.z; uo[j][1] = u.w;
                }
                #pragma unroll
                for (int j = 0; j < 4; j++) mma_bf16(oacc[ng*4 + j], phe, ue[j]);
                #pragma unroll
                for (int j = 0; j < 4; j++) mma_bf16(oacc[ng*4 + j], pho, uo[j]);
            }
        }
    }

    // ---- Epilogue: split-store directly into O-proj A-fragment planes ----
    const float inv0 = 1.0f / l0;
    const float inv1 = 1.0f / l1;
    const size_t cbase = (size_t)(b * 16 + qt) * NCH;
    #pragma unroll
    for (int n = 0; n < 16; n++) {
        const int c = h * 8 + (n >> 1);
        const size_t off = ((cbase + c) * 8 + w) * 512 + (size_t)(g * 4 + t4) * 16;
        uint32_t uh0, ul0, uh1, ul1;
        split2(oacc[n][0] * inv0, oacc[n][1] * inv0, uh0, ul0);
        split2(oacc[n][2] * inv1, oacc[n][3] * inv1, uh1, ul1);
        const int j0 = (2 * (n & 1)) * 4;
        const int j1 = (1 + 2 * (n & 1)) * 4;
        *(uint32_t*)((char*)acPh + off + j0) = uh0;
        *(uint32_t*)((char*)acPh + off + j1) = uh1;
        *(uint32_t*)((char*)acPl + off + j0) = ul0;
        *(uint32_t*)((char*)acPl + off + j1) = ul1;
    }
}

// ---------------------------------------------------------------------------
// Launch
// ---------------------------------------------------------------------------
extern "C" void kernel_launch(void* const* d_in, const int* in_sizes, int n_in,
                              void* d_out, int out_size)
{
    (void)in_sizes; (void)n_in; (void)out_size;
    const float* query = (const float*)d_in[0];
    const float* key   = (const float*)d_in[1];
    const float* value = (const float*)d_in[2];
    const int*   mask  = (const int*)  d_in[3];
    const float* Wq    = (const float*)d_in[4];
    const float* Wk    = (const float*)d_in[5];
    const float* Wv    = (const float*)d_in[6];
    const float* Wo    = (const float*)d_in[7];
    float* out = (float*)d_out;

    __nv_bfloat16 *aq_h, *aq_l, *ak_h, *ak_l, *av_h, *av_l, *ac_h, *ac_l;
    __nv_bfloat16 *wq_h, *wq_l, *wk_h, *wk_l, *wv_h, *wv_l, *wo_h, *wo_l;
    __nv_bfloat16 *qa_h, *qa_l, *kb_h, *kb_l, *vb_h, *vb_l;
    uint32_t* mb;
    cudaGetSymbolAddress((void**)&aq_h, g_aq_h); cudaGetSymbolAddress((void**)&aq_l, g_aq_l);
    cudaGetSymbolAddress((void**)&ak_h, g_ak_h); cudaGetSymbolAddress((void**)&ak_l, g_ak_l);
    cudaGetSymbolAddress((void**)&av_h, g_av_h); cudaGetSymbolAddress((void**)&av_l, g_av_l);
    cudaGetSymbolAddress((void**)&ac_h, g_ac_h); cudaGetSymbolAddress((void**)&ac_l, g_ac_l);
    cudaGetSymbolAddress((void**)&wq_h, g_wq_h); cudaGetSymbolAddress((void**)&wq_l, g_wq_l);
    cudaGetSymbolAddress((void**)&wk_h, g_wk_h); cudaGetSymbolAddress((void**)&wk_l, g_wk_l);
    cudaGetSymbolAddress((void**)&wv_h, g_wv_h); cudaGetSymbolAddress((void**)&wv_l, g_wv_l);
    cudaGetSymbolAddress((void**)&wo_h, g_wo_h); cudaGetSymbolAddress((void**)&wo_l, g_wo_l);
    cudaGetSymbolAddress((void**)&qa_h, g_qa_h); cudaGetSymbolAddress((void**)&qa_l, g_qa_l);
    cudaGetSymbolAddress((void**)&kb_h, g_kb_h); cudaGetSymbolAddress((void**)&kb_l, g_kb_l);
    cudaGetSymbolAddress((void**)&vb_h, g_vb_h); cudaGetSymbolAddress((void**)&vb_l, g_vb_l);
    cudaGetSymbolAddress((void**)&mb,   g_mb);

    cudaFuncSetAttribute(qkv_gemm, cudaFuncAttributeMaxDynamicSharedMemorySize, GEMM_SMEM);
    cudaFuncSetAttribute(tc_gemm0, cudaFuncAttributeMaxDynamicSharedMemorySize, GEMM_SMEM);
    cudaFuncSetAttribute(gqa_attn_mma, cudaFuncAttributeMaxDynamicSharedMemorySize, ATT_SMEM);

    // Pack mask to bits
    pack_mask<<<(PB * PS * PS) / 256, 256>>>(mask, mb);

    // Pack all four weights in one launch
    pack_w4<<<10240, dim3(32, 8)>>>(Wq, Wk, Wv, Wo,
                                    wq_h, wq_l, wk_h, wk_l, wv_h, wv_l, wo_h, wo_l);

    // Pack all three input activations in one launch
    pack_a3<<<3 * PACKA_BLOCKS_PER, 256>>>(query, key, value,
                                           aq_h, aq_l, ak_h, ak_l, av_h, av_l);

    // Merged Q/K/V projections (V epilogue packs V B-planes directly)
    qkv_gemm<<<dim3(24, PM / 128), 256, GEMM_SMEM>>>(
        aq_h, aq_l, ak_h, ak_l, av_h, av_l,
        wq_h, wq_l, wk_h, wk_l, wv_h, wv_l,
        qa_h, qa_l, kb_h, kb_l, vb_h, vb_l);

    // Tensor-core fused attention (BK=32, 2 CTAs/SM) — writes O-proj A-planes
    gqa_attn_mma<<<dim3(PS / 128, PH, PB), 256, ATT_SMEM>>>(
        qa_h, qa_l, kb_h, kb_l, vb_h, vb_l, mb, ac_h, ac_l);

    // Output projection
    tc_gemm0<<<dim3(PD / 128, PM / 128), 256, GEMM_SMEM>>>(
        ac_h, ac_l, wo_h, wo_l, out, PD);
}

// round 17
// speedup vs baseline: 1.1243x; 1.1243x over previous
#include <cuda_runtime.h>
#include <cuda_bf16.h>
#include <cstdint>

// Problem constants
#define PB   2
#define PS   2048
#define PD   2048
#define PH   16
#define PHKV 4
#define PDH  128
#define PKVD (PHKV * PDH)   // 512
#define PM   (PB * PS)      // 4096
#define NCH  (PD / 16)      // 128 k16-chunks for GEMM

// ---------------------------------------------------------------------------
// Scratch (device globals: no allocations allowed)
// ---------------------------------------------------------------------------
#define A_PLANE_ELEMS  ((size_t)PM * PD)
#define WQ_PLANE_ELEMS ((size_t)PD * PD)
#define WK_PLANE_ELEMS ((size_t)PD * PKVD)
__device__ __align__(128) __nv_bfloat16 g_aq_h[A_PLANE_ELEMS],  g_aq_l[A_PLANE_ELEMS];
__device__ __align__(128) __nv_bfloat16 g_ak_h[A_PLANE_ELEMS],  g_ak_l[A_PLANE_ELEMS];
__device__ __align__(128) __nv_bfloat16 g_av_h[A_PLANE_ELEMS],  g_av_l[A_PLANE_ELEMS];
__device__ __align__(128) __nv_bfloat16 g_ac_h[A_PLANE_ELEMS],  g_ac_l[A_PLANE_ELEMS];
__device__ __align__(128) __nv_bfloat16 g_wq_h[WQ_PLANE_ELEMS], g_wq_l[WQ_PLANE_ELEMS];
__device__ __align__(128) __nv_bfloat16 g_wo_h[WQ_PLANE_ELEMS], g_wo_l[WQ_PLANE_ELEMS];
__device__ __align__(128) __nv_bfloat16 g_wk_h[WK_PLANE_ELEMS], g_wk_l[WK_PLANE_ELEMS];
__device__ __align__(128) __nv_bfloat16 g_wv_h[WK_PLANE_ELEMS], g_wv_l[WK_PLANE_ELEMS];

// Attention packed planes (paired-k16 fragment order, kt64 tiles)
__device__ __align__(128) __nv_bfloat16 g_qa_h[(size_t)PM * PD],   g_qa_l[(size_t)PM * PD];
__device__ __align__(128) __nv_bfloat16 g_kb_h[(size_t)PM * PKVD], g_kb_l[(size_t)PM * PKVD];
__device__ __align__(128) __nv_bfloat16 g_vb_h[(size_t)PM * PKVD], g_vb_l[(size_t)PM * PKVD];

// Bit-packed mask: 1 bit per (b, s, k)
__device__ __align__(128) uint32_t g_mb[(size_t)PB * PS * PS / 32];   // 1 MB

// ---------------------------------------------------------------------------
// Helpers
// ---------------------------------------------------------------------------
__device__ __forceinline__ uint32_t smem_u32(const void* p) {
    uint32_t a;
    asm("{ .reg .u64 t; cvta.to.shared.u64 t, %1; cvt.u32.u64 %0, t; }"
        : "=r"(a) : "l"(p));
    return a;
}

__device__ __forceinline__ void cp16(uint32_t dst, const void* src) {
    asm volatile("cp.async.cg.shared.global [%0], [%1], 16;"
                 :: "r"(dst), "l"(src) : "memory");
}

__device__ __forceinline__ void mma_bf16(float* c, const uint32_t* a, const uint32_t* b) {
    asm volatile(
        "mma.sync.aligned.m16n8k16.row.col.f32.bf16.bf16.f32 "
        "{%0,%1,%2,%3}, {%4,%5,%6,%7}, {%8,%9}, {%0,%1,%2,%3};"
        : "+f"(c[0]), "+f"(c[1]), "+f"(c[2]), "+f"(c[3])
        : "r"(a[0]), "r"(a[1]), "r"(a[2]), "r"(a[3]),
          "r"(b[0]), "r"(b[1]));
}

__device__ __forceinline__ float ex2f(float x) {
    float r;
    asm("ex2.approx.f32 %0, %1;" : "=f"(r) : "f"(x));
    return r;
}

__device__ __forceinline__ void split2(float f0, float f1, uint32_t& uh, uint32_t& ul) {
    asm("cvt.rn.bf16x2.f32 %0, %1, %2;" : "=r"(uh) : "f"(f1), "f"(f0));
    float h0 = __uint_as_float(uh << 16);
    float h1 = __uint_as_float(uh & 0xFFFF0000u);
    float l0 = f0 - h0, l1 = f1 - h1;
    asm("cvt.rn.bf16x2.f32 %0, %1, %2;" : "=r"(ul) : "f"(l1), "f"(l0));
}

// ---------------------------------------------------------------------------
// pack_mask: int32 mask -> bit mask (warp ballot)
// ---------------------------------------------------------------------------
__global__ void pack_mask(const int* __restrict__ mask, uint32_t* __restrict__ bits)
{
    const int i = blockIdx.x * 256 + threadIdx.x;
    const int v = mask[i];
    const uint32_t b = __ballot_sync(0xffffffffu, v != 0);
    if ((threadIdx.x & 31) == 0) bits[i >> 5] = b;
}

// ---------------------------------------------------------------------------
// pack_a3: q/k/v inputs -> A-fragment hi/lo planes, one launch.
// ---------------------------------------------------------------------------
#define PACKA_BLOCKS_PER 8192   // (PM*PD/4)/256

__global__ void pack_a3(const float* __restrict__ q, const float* __restrict__ k,
                        const float* __restrict__ v,
                        __nv_bfloat16* __restrict__ qhp, __nv_bfloat16* __restrict__ qlp,
                        __nv_bfloat16* __restrict__ khp, __nv_bfloat16* __restrict__ klp,
                        __nv_bfloat16* __restrict__ vhp, __nv_bfloat16* __restrict__ vlp)
{
    const int which = blockIdx.x >> 13;
    const int inner = blockIdx.x & 8191;
    const float* src = (which == 0) ? q : (which == 1) ? k : v;
    __nv_bfloat16* hi = (which == 0) ? qhp : (which == 1) ? khp : vhp;
    __nv_bfloat16* lo = (which == 0) ? qlp : (which == 1) ? klp : vlp;

    int idx = inner * 256 + threadIdx.x;
    int c2 = idx & 1023;
    int mg = idx >> 10;
    int g  = mg & 7;
    int mt = (mg >> 3) & 7;
    int R  = mg >> 6;
    int m  = R * 128 + mt * 16 + g;
    int kcol = c2 * 2;
    int c  = kcol >> 4, kk = kcol & 15;
    int t4 = (kk >> 1) & 3, khi = kk >> 3;

    float2 f0 = ((const float2*)(src + (size_t)m * PD))[c2];
    float2 f1 = ((const float2*)(src + (size_t)(m + 8) * PD))[c2];
    uint32_t uh0, ul0, uh1, ul1;
    split2(f0.x, f0.y, uh0, ul0);
    split2(f1.x, f1.y, uh1, ul1);

    size_t off = (((size_t)R * NCH + c) * 8 + mt) * 512
               + (size_t)(g * 4 + t4) * 16 + khi * 8;
    *(uint2*)((char*)hi + off) = make_uint2(uh0, uh1);
    *(uint2*)((char*)lo + off) = make_uint2(ul0, ul1);
}

// ---------------------------------------------------------------------------
// pack_w4: all four weights -> B-fragment hi/lo planes, one launch.
// ---------------------------------------------------------------------------
__global__ void pack_w4(const float* __restrict__ Wq, const float* __restrict__ Wk,
                        const float* __restrict__ Wv, const float* __restrict__ Wo,
                        __nv_bfloat16* __restrict__ qh, __nv_bfloat16* __restrict__ ql,
                        __nv_bfloat16* __restrict__ kh, __nv_bfloat16* __restrict__ kl,
                        __nv_bfloat16* __restrict__ vh, __nv_bfloat16* __restrict__ vl,
                        __nv_bfloat16* __restrict__ oh, __nv_bfloat16* __restrict__ ol)
{
    __shared__ float t[32][33];
    const int tx = threadIdx.x, ty = threadIdx.y;

    int i = blockIdx.x;
    const float* w; __nv_bfloat16 *hi, *lo; int N, bxn, byk;
    if (i < 4096)      { w = Wq; hi = qh; lo = ql; N = PD;   bxn = i & 63; byk = i >> 6; }
    else if (i < 5120) { i -= 4096; w = Wk; hi = kh; lo = kl; N = PKVD; bxn = i & 15; byk = i >> 4; }
    else if (i < 6144) { i -= 5120; w = Wv; hi = vh; lo = vl; N = PKVD; bxn = i & 15; byk = i >> 4; }
    else               { i -= 6144; w = Wo; hi = oh; lo = ol; N = PD;   bxn = i & 63; byk = i >> 6; }

    const int nx = bxn * 32, k0 = byk * 32;

    #pragma unroll
    for (int j = 0; j < 32; j += 8)
        t[ty + j][tx] = w[(size_t)(k0 + ty + j) * N + nx + tx];
    __syncthreads();

    if (tx < 16) {
        const int k  = k0 + 2 * tx;
        const int c  = k >> 4, kk = k & 15;
        const int t4 = (kk >> 1) & 3, khi = kk >> 3;
        #pragma unroll
        for (int j = 0; j < 32; j += 8) {
            const int n = nx + ty + j;
            uint32_t uh, ul;
            split2(t[2 * tx][ty + j], t[2 * tx + 1][ty + j], uh, ul);
            const int NT = n >> 7, nn = n & 127;
            const int ntile = nn >> 3, g = nn & 7;
            const int lane = g * 4 + t4;
            size_t off = (((size_t)NT * NCH + c) * 16 + ntile) * 256 + lane * 8 + khi * 4;
            *(uint32_t*)((char*)hi + off) = uh;
            *(uint32_t*)((char*)lo + off) = ul;
        }
    }
}

// ---------------------------------------------------------------------------
// GEMM mainloop body (macro) — validated R11/R12
// ---------------------------------------------------------------------------
#define GNSTG      3
#define SUB_BYTES  16384
#define GSTG_BYTES 32768
#define GEMM_SMEM  (GNSTG * GSTG_BYTES)   // 98304

#define GEMM_MAINLOOP()                                                         \
    const uint32_t sbase = smem_u32(dsm);                                       \
    const int t16 = tid * 16;                                                   \
    _Pragma("unroll")                                                           \
    for (int s = 0; s < GNSTG - 1; s++) {                                       \
        _Pragma("unroll")                                                       \
        for (int hf = 0; hf < 2; hf++) {                                        \
            const uint32_t d = sbase + s * GSTG_BYTES + hf * SUB_BYTES + t16;   \
            const size_t o = (size_t)(s * 2 + hf) * 4096 + t16;                 \
            cp16(d,         pAh + o);                                           \
            cp16(d + 4096,  pAl + o);                                           \
            cp16(d + 8192,  pBh + o);                                           \
            cp16(d + 12288, pBl + o);                                           \
        }                                                                       \
        asm volatile("cp.async.commit_group;" ::: "memory");                    \
    }                                                                           \
    _Pragma("unroll")                                                           \
    for (int mt = 0; mt < 4; mt++)                                              \
        _Pragma("unroll")                                                       \
        for (int nt = 0; nt < 4; nt++)                                          \
            _Pragma("unroll")                                                   \
            for (int j = 0; j < 4; j++) acc[mt][nt][j] = 0.0f;                  \
    for (int pc = 0; pc < NCH / 2; pc++) {                                      \
        asm volatile("cp.async.wait_group 1;" ::: "memory");                    \
        __syncthreads();                                                        \
        const int np = pc + GNSTG - 1;                                          \
        if (np < NCH / 2) {                                                     \
            _Pragma("unroll")                                                   \
            for (int hf = 0; hf < 2; hf++) {                                    \
                const uint32_t d = sbase + (np % GNSTG) * GSTG_BYTES            \
                                 + hf * SUB_BYTES + t16;                        \
                const size_t o = (size_t)(np * 2 + hf) * 4096 + t16;            \
                cp16(d,         pAh + o);                                       \
                cp16(d + 4096,  pAl + o);                                       \
                cp16(d + 8192,  pBh + o);                                       \
                cp16(d + 12288, pBl + o);                                       \
            }                                                                   \
        }                                                                       \
        asm volatile("cp.async.commit_group;" ::: "memory");                    \
        _Pragma("unroll")                                                       \
        for (int hf = 0; hf < 2; hf++) {                                        \
            const char* stg = dsm + (pc % GNSTG) * GSTG_BYTES + hf * SUB_BYTES; \
            const uint4* sAh = (const uint4*)(stg);                             \
            const uint4* sAl = (const uint4*)(stg + 4096);                      \
            const uint2* sBh = (const uint2*)(stg + 8192);                      \
            const uint2* sBl = (const uint2*)(stg + 12288);                     \
            uint32_t ahi[4][4], alo[4][4], bfr[4][2];                           \
            _Pragma("unroll")                                                   \
            for (int mt = 0; mt < 4; mt++) {                                    \
                uint4 h = sAh[(warp_m * 4 + mt) * 32 + lane];                   \
                ahi[mt][0] = h.x; ahi[mt][1] = h.y;                             \
                ahi[mt][2] = h.z; ahi[mt][3] = h.w;                             \
                uint4 l = sAl[(warp_m * 4 + mt) * 32 + lane];                   \
                alo[mt][0] = l.x; alo[mt][1] = l.y;                             \
                alo[mt][2] = l.z; alo[mt][3] = l.w;                             \
            }                                                                   \
            _Pragma("unroll")                                                   \
            for (int nt = 0; nt < 4; nt++) {                                    \
                uint2 h = sBh[(warp_n * 4 + nt) * 32 + lane];                   \
                bfr[nt][0] = h.x; bfr[nt][1] = h.y;                             \
            }                                                                   \
            _Pragma("unroll")                                                   \
            for (int mt = 0; mt < 4; mt++)                                      \
                _Pragma("unroll")                                               \
                for (int nt = 0; nt < 4; nt++)                                  \
                    mma_bf16(acc[mt][nt], ahi[mt], bfr[nt]);                    \
            _Pragma("unroll")                                                   \
            for (int mt = 0; mt < 4; mt++)                                      \
                _Pragma("unroll")                                               \
                for (int nt = 0; nt < 4; nt++)                                  \
                    mma_bf16(acc[mt][nt], alo[mt], bfr[nt]);                    \
            _Pragma("unroll")                                                   \
            for (int nt = 0; nt < 4; nt++) {                                    \
                uint2 l = sBl[(warp_n * 4 + nt) * 32 + lane];                   \
                bfr[nt][0] = l.x; bfr[nt][1] = l.y;                             \
            }                                                                   \
            _Pragma("unroll")                                                   \
            for (int mt = 0; mt < 4; mt++)                                      \
                _Pragma("unroll")                                               \
                for (int nt = 0; nt < 4; nt++)                                  \
                    mma_bf16(acc[mt][nt], ahi[mt], bfr[nt]);                    \
        }                                                                       \
    }

// ---------------------------------------------------------------------------
// Merged Q/K/V projection GEMM (kt64 attention plane layouts — R14)
// ---------------------------------------------------------------------------
__global__ __launch_bounds__(256, 2)
void qkv_gemm(const __nv_bfloat16* __restrict__ aqh, const __nv_bfloat16* __restrict__ aql,
              const __nv_bfloat16* __restrict__ akh, const __nv_bfloat16* __restrict__ akl,
              const __nv_bfloat16* __restrict__ avh, const __nv_bfloat16* __restrict__ avl,
              const __nv_bfloat16* __restrict__ wqh, const __nv_bfloat16* __restrict__ wql,
              const __nv_bfloat16* __restrict__ wkh, const __nv_bfloat16* __restrict__ wkl,
              const __nv_bfloat16* __restrict__ wvh, const __nv_bfloat16* __restrict__ wvl,
              __nv_bfloat16* __restrict__ qaPh, __nv_bfloat16* __restrict__ qaPl,
              __nv_bfloat16* __restrict__ kbPh, __nv_bfloat16* __restrict__ kbPl,
              __nv_bfloat16* __restrict__ vbPh, __nv_bfloat16* __restrict__ vbPl)
{
    extern __shared__ char dsm[];
    const int tid  = threadIdx.x;
    const int lane = tid & 31;
    const int wid  = tid >> 5;
    const int warp_m = wid >> 2;
    const int warp_n = wid & 3;
    const int bx = blockIdx.x;
    const int mt0 = blockIdx.y;

    int mode, nt0;
    const __nv_bfloat16 *Ah, *Al, *Bh, *Bl;
    if (bx < 16)      { mode = 1; nt0 = bx;      Ah = aqh; Al = aql; Bh = wqh; Bl = wql; }
    else if (bx < 20) { mode = 2; nt0 = bx - 16; Ah = akh; Al = akl; Bh = wkh; Bl = wkl; }
    else              { mode = 0; nt0 = bx - 20; Ah = avh; Al = avl; Bh = wvh; Bl = wvl; }

    const char* pAh = (const char*)Ah + (size_t)mt0 * NCH * 4096;
    const char* pAl = (const char*)Al + (size_t)mt0 * NCH * 4096;
    const char* pBh = (const char*)Bh + (size_t)nt0 * NCH * 4096;
    const char* pBl = (const char*)Bl + (size_t)nt0 * NCH * 4096;

    float acc[4][4][4];
    GEMM_MAINLOOP();

    const int g  = lane >> 2;
    const int t4 = lane & 3;

    if (mode == 0) {
        // ---- V epilogue: stage fp32 tile to smem, pack to kt64 V B-planes ----
        asm volatile("cp.async.wait_group 0;" ::: "memory");
        __syncthreads();
        float* sC = (float*)dsm;   // [128][129]
        #pragma unroll
        for (int mt = 0; mt < 4; mt++) {
            #pragma unroll
            for (int nt = 0; nt < 4; nt++) {
                const int r = warp_m * 64 + mt * 16 + g;
                const int c = warp_n * 32 + nt * 8 + 2 * t4;
                sC[r * 129 + c]           = acc[mt][nt][0];
                sC[r * 129 + c + 1]       = acc[mt][nt][1];
                sC[(r + 8) * 129 + c]     = acc[mt][nt][2];
                sC[(r + 8) * 129 + c + 1] = acc[mt][nt][3];
            }
        }
        __syncthreads();

        const int gkv = nt0;
        const int b   = mt0 >> 4;
        #pragma unroll
        for (int i = 0; i < 32; i++) {
            const int wI = i * 256 + tid;
            const int d  = wI & 127;
            const int rp = wI >> 7;
            const int sl = rp * 2;
            float f0 = sC[sl * 129 + d];
            float f1 = sC[(sl + 1) * 129 + d];
            uint32_t uh, ul;
            split2(f0, f1, uh, ul);

            const int sg  = mt0 * 128 + sl;
            const int sin = sg & 2047;
            const int kt  = sin >> 6, sk = sin & 63;
            const int k16 = sk >> 4, kk = sk & 15;
            const int t4v = (kk >> 1) & 3, khiv = kk >> 3;
            const int n8 = d >> 3, gN = d & 7;
            size_t off = ((size_t)(b * PHKV + gkv) * 32 + kt) * 16384
                       + (size_t)(n8 * 2 + (k16 >> 1)) * 512
                       + (gN * 4 + t4v) * 16 + (k16 & 1) * 8 + khiv * 4;
            *(uint32_t*)((char*)vbPh + off) = uh;
            *(uint32_t*)((char*)vbPl + off) = ul;
        }
        return;
    }

    #pragma unroll
    for (int mt = 0; mt < 4; mt++) {
        #pragma unroll
        for (int nt = 0; nt < 4; nt++) {
            const int row0 = mt0 * 128 + warp_m * 64 + mt * 16 + g;
            const int col0 = nt0 * 128 + warp_n * 32 + nt * 8 + 2 * t4;

            if (mode == 1) {
                const float scale = 0.08838834764831845f * 1.4426950408889634f;
                const int bb = row0 >> 11, s = row0 & 2047;
                const int qt = s >> 7, rr = s & 127;
                const int wq_ = rr >> 4;
                const int hh = col0 >> 7, d = col0 & 127;
                const int k16 = d >> 4, khi = (d >> 3) & 1;
                size_t base = (((((size_t)(bb * PH + hh) * 16 + qt) * 8 + wq_) * 8 + k16) * 512)
                            + (size_t)(g * 4 + t4) * 16;
                uint32_t uh0, ul0, uh1, ul1;
                split2(acc[mt][nt][0] * scale, acc[mt][nt][1] * scale, uh0, ul0);
                split2(acc[mt][nt][2] * scale, acc[mt][nt][3] * scale, uh1, ul1);
                *(uint32_t*)((char*)qaPh + base + (2 * khi) * 4)     = uh0;
                *(uint32_t*)((char*)qaPh + base + (1 + 2 * khi) * 4) = uh1;
                *(uint32_t*)((char*)qaPl + base + (2 * khi) * 4)     = ul0;
                *(uint32_t*)((char*)qaPl + base + (1 + 2 * khi) * 4) = ul1;
            } else {
                const int bb = row0 >> 11, s = row0 & 2047;
                const int kt = s >> 6, sk = s & 63;
                const int n8 = sk >> 3;
                const int gkv = col0 >> 7, d = col0 & 127;
                const int k16 = d >> 4, khi = (d >> 3) & 1;
                size_t base = ((size_t)(bb * PHKV + gkv) * 32 + kt) * 16384
                            + (size_t)(n8 * 4 + (k16 >> 1)) * 512
                            + (size_t)(g * 4 + t4) * 16 + (k16 & 1) * 8 + khi * 4;
                uint32_t uh0, ul0, uh1, ul1;
                split2(acc[mt][nt][0], acc[mt][nt][1], uh0, ul0);
                split2(acc[mt][nt][2], acc[mt][nt][3], uh1, ul1);
                *(uint32_t*)((char*)kbPh + base)        = uh0;
                *(uint32_t*)((char*)kbPh + base + 2048) = uh1;
                *(uint32_t*)((char*)kbPl + base)        = ul0;
                *(uint32_t*)((char*)kbPl + base + 2048) = ul1;
            }
        }
    }
}

// ---------------------------------------------------------------------------
// Plain GEMM for O-projection (fp32 C out)
// ---------------------------------------------------------------------------
__global__ __launch_bounds__(256, 2)
void tc_gemm0(const __nv_bfloat16* __restrict__ Ah, const __nv_bfloat16* __restrict__ Al,
              const __nv_bfloat16* __restrict__ Bh, const __nv_bfloat16* __restrict__ Bl,
              float* __restrict__ C, int N)
{
    extern __shared__ char dsm[];
    const int tid  = threadIdx.x;
    const int lane = tid & 31;
    const int wid  = tid >> 5;
    const int warp_m = wid >> 2;
    const int warp_n = wid & 3;
    const int mt0 = blockIdx.y, nt0 = blockIdx.x;

    const char* pAh = (const char*)Ah + (size_t)mt0 * NCH * 4096;
    const char* pAl = (const char*)Al + (size_t)mt0 * NCH * 4096;
    const char* pBh = (const char*)Bh + (size_t)nt0 * NCH * 4096;
    const char* pBl = (const char*)Bl + (size_t)nt0 * NCH * 4096;

    float acc[4][4][4];
    GEMM_MAINLOOP();

    const int g  = lane >> 2;
    const int t4 = lane & 3;
    #pragma unroll
    for (int mt = 0; mt < 4; mt++) {
        #pragma unroll
        for (int nt = 0; nt < 4; nt++) {
            const int row0 = mt0 * 128 + warp_m * 64 + mt * 16 + g;
            const int col0 = nt0 * 128 + warp_n * 32 + nt * 8 + 2 * t4;
            float* Cp = C + (size_t)row0 * N + col0;
            *(float2*)(Cp)                 = make_float2(acc[mt][nt][0], acc[mt][nt][1]);
            *(float2*)(Cp + (size_t)8 * N) = make_float2(acc[mt][nt][2], acc[mt][nt][3]);
        }
    }
}

// ---------------------------------------------------------------------------
// Tensor-core fused GQA flash attention (bf16-S3), BK=64, 3-stage pipeline.
// NO online max (fixed reference 0, safe: |s_log2| <= ~51 << fp32 range),
// deferred l-reduction to epilogue => zero per-iteration shuffles/rescale.
// ---------------------------------------------------------------------------
#define ATT_STG    65536
#define ATT_SMEM   (3 * ATT_STG)   // 196608

__global__ __launch_bounds__(256, 1)
void gqa_attn_mma(const __nv_bfloat16* __restrict__ Qh, const __nv_bfloat16* __restrict__ Ql,
                  const __nv_bfloat16* __restrict__ Kh, const __nv_bfloat16* __restrict__ Kl,
                  const __nv_bfloat16* __restrict__ Vh, const __nv_bfloat16* __restrict__ Vl,
                  const uint32_t* __restrict__ mbits,
                  __nv_bfloat16* __restrict__ acPh, __nv_bfloat16* __restrict__ acPl)
{
    extern __shared__ char dsm[];
    const int tid  = threadIdx.x;
    const int lane = tid & 31;
    const int w    = tid >> 5;
    const int g    = lane >> 2;
    const int t4   = lane & 3;
    const int qt   = blockIdx.x;
    const int h    = blockIdx.y;
    const int b    = blockIdx.z;
    const int gkv  = h >> 2;

    uint32_t qh[8][4], ql[8][4];
    {
        const size_t qoff = (((((size_t)(b * PH + h) * 16 + qt) * 8 + w) * 8) * 512)
                          + (size_t)lane * 16;
        const char* qb  = (const char*)Qh + qoff;
        const char* qb2 = (const char*)Ql + qoff;
        #pragma unroll
        for (int k16 = 0; k16 < 8; k16++) {
            uint4 v = *(const uint4*)(qb + k16 * 512);
            qh[k16][0] = v.x; qh[k16][1] = v.y; qh[k16][2] = v.z; qh[k16][3] = v.w;
            uint4 u = *(const uint4*)(qb2 + k16 * 512);
            ql[k16][0] = u.x; ql[k16][1] = u.y; ql[k16][2] = u.z; ql[k16][3] = u.w;
        }
    }

    float oacc[16][4];
    #pragma unroll
    for (int n = 0; n < 16; n++)
        #pragma unroll
        for (int j = 0; j < 4; j++) oacc[n][j] = 0.0f;
    float l0 = 0.0f, l1 = 0.0f;   // per-lane partial row sums

    const size_t kvPlane = ((size_t)(b * PHKV + gkv) * 32);
    const char* pKh = (const char*)Kh + kvPlane * 16384;
    const char* pKl = (const char*)Kl + kvPlane * 16384;
    const char* pVh = (const char*)Vh + kvPlane * 16384;
    const char* pVl = (const char*)Vl + kvPlane * 16384;

    const uint32_t sbase = smem_u32(dsm);
    const int t16 = tid * 16;

    #pragma unroll
    for (int s = 0; s < 2; s++) {
        const uint32_t dst = sbase + s * ATT_STG;
        const size_t go = (size_t)s * 16384;
        #pragma unroll
        for (int i = 0; i < 4; i++) {
            const int o = t16 + i * 4096;
            cp16(dst + o,         pKh + go + o);
            cp16(dst + 16384 + o, pKl + go + o);
            cp16(dst + 32768 + o, pVh + go + o);
            cp16(dst + 49152 + o, pVl + go + o);
        }
        asm volatile("cp.async.commit_group;" ::: "memory");
    }

    const int r0 = qt * 128 + w * 16 + g;
    const int r1 = r0 + 8;
    const uint2* mrow0 = (const uint2*)(mbits + (size_t)(b * PS + r0) * (PS / 32));
    const uint2* mrow1 = (const uint2*)(mbits + (size_t)(b * PS + r1) * (PS / 32));

    for (int kt = 0; kt < 32; kt++) {
        const uint2 mb0 = mrow0[kt];
        const uint2 mb1 = mrow1[kt];

        asm volatile("cp.async.wait_group 1;" ::: "memory");
        __syncthreads();

        if (kt + 2 < 32) {
            const uint32_t dst = sbase + ((kt + 2) % 3) * ATT_STG;
            const size_t go = (size_t)(kt + 2) * 16384;
            #pragma unroll
            for (int i = 0; i < 4; i++) {
                const int o = t16 + i * 4096;
                cp16(dst + o,         pKh + go + o);
                cp16(dst + 16384 + o, pKl + go + o);
                cp16(dst + 32768 + o, pVh + go + o);
                cp16(dst + 49152 + o, pVl + go + o);
            }
        }
        asm volatile("cp.async.commit_group;" ::: "memory");

        const char* stg = dsm + (kt % 3) * ATT_STG;
        const char* sKh = stg;
        const char* sKl = stg + 16384;
        const char* sVh = stg + 32768;
        const char* sVl = stg + 49152;

        // ---- S = Q K^T (3-term), paired-k16 LDS.128 loads ----
        float sm[8][4];
        #pragma unroll
        for (int n = 0; n < 8; n++)
            #pragma unroll
            for (int j = 0; j < 4; j++) sm[n][j] = 0.0f;

        #pragma unroll
        for (int kp = 0; kp < 4; kp++) {
            uint32_t be[8][2], bo[8][2];
            #pragma unroll
            for (int n = 0; n < 8; n++) {
                uint4 v = *(const uint4*)(sKh + (n * 4 + kp) * 512 + lane * 16);
                be[n][0] = v.x; be[n][1] = v.y; bo[n][0] = v.z; bo[n][1] = v.w;
            }
            #pragma unroll
            for (int n = 0; n < 8; n++) mma_bf16(sm[n], qh[2*kp],   be[n]);
            #pragma unroll
            for (int n = 0; n < 8; n++) mma_bf16(sm[n], qh[2*kp+1], bo[n]);
            #pragma unroll
            for (int n = 0; n < 8; n++) mma_bf16(sm[n], ql[2*kp],   be[n]);
            #pragma unroll
            for (int n = 0; n < 8; n++) mma_bf16(sm[n], ql[2*kp+1], bo[n]);
            #pragma unroll
            for (int n = 0; n < 8; n++) {
                uint4 u = *(const uint4*)(sKl + (n * 4 + kp) * 512 + lane * 16);
                be[n][0] = u.x; be[n][1] = u.y; bo[n][0] = u.z; bo[n][1] = u.w;
            }
            #pragma unroll
            for (int n = 0; n < 8; n++) mma_bf16(sm[n], qh[2*kp],   be[n]);
            #pragma unroll
            for (int n = 0; n < 8; n++) mma_bf16(sm[n], qh[2*kp+1], bo[n]);
        }

        // ---- bit-mask + p = ex2(s); accumulate per-lane partial sums ----
        #pragma unroll
        for (int n = 0; n < 8; n++) {
            const uint32_t w0 = (n < 4) ? mb0.x : mb0.y;
            const uint32_t w1 = (n < 4) ? mb1.x : mb1.y;
            const int sh = 2 * t4 + 8 * (n & 3);
            if (!((w0 >> sh) & 1u))       sm[n][0] = -1e9f;
            if (!((w0 >> (sh + 1)) & 1u)) sm[n][1] = -1e9f;
            if (!((w1 >> sh) & 1u))       sm[n][2] = -1e9f;
            if (!((w1 >> (sh + 1)) & 1u)) sm[n][3] = -1e9f;
            sm[n][0] = ex2f(sm[n][0]); l0 += sm[n][0];
            sm[n][1] = ex2f(sm[n][1]); l0 += sm[n][1];
            sm[n][2] = ex2f(sm[n][2]); l1 += sm[n][2];
            sm[n][3] = ex2f(sm[n][3]); l1 += sm[n][3];
        }

        // ---- O += P V (3-term), paired-k16 LDS.128 loads ----
        #pragma unroll
        for (int kp = 0; kp < 2; kp++) {
            uint32_t phe[4], ple[4], pho[4], plo[4];
            split2(sm[4*kp][0],   sm[4*kp][1],   phe[0], ple[0]);
            split2(sm[4*kp][2],   sm[4*kp][3],   phe[1], ple[1]);
            split2(sm[4*kp+1][0], sm[4*kp+1][1], phe[2], ple[2]);
            split2(sm[4*kp+1][2], sm[4*kp+1][3], phe[3], ple[3]);
            split2(sm[4*kp+2][0], sm[4*kp+2][1], pho[0], plo[0]);
            split2(sm[4*kp+2][2], sm[4*kp+2][3], pho[1], plo[1]);
            split2(sm[4*kp+3][0], sm[4*kp+3][1], pho[2], plo[2]);
            split2(sm[4*kp+3][2], sm[4*kp+3][3], pho[3], plo[3]);

            #pragma unroll
            for (int ng = 0; ng < 4; ng++) {
                uint32_t ve[4][2], vo[4][2];
                #pragma unroll
                for (int j = 0; j < 4; j++) {
                    uint4 v = *(const uint4*)(sVh + ((ng*4 + j) * 2 + kp) * 512 + lane * 16);
                    ve[j][0] = v.x; ve[j][1] = v.y; vo[j][0] = v.z; vo[j][1] = v.w;
                }
                #pragma unroll
                for (int j = 0; j < 4; j++) mma_bf16(oacc[ng*4 + j], phe, ve[j]);
                #pragma unroll
                for (int j = 0; j < 4; j++) mma_bf16(oacc[ng*4 + j], pho, vo[j]);
                #pragma unroll
                for (int j = 0; j < 4; j++) mma_bf16(oacc[ng*4 + j], ple, ve[j]);
                #pragma unroll
                for (int j = 0; j < 4; j++) mma_bf16(oacc[ng*4 + j], plo, vo[j]);
            }
            #pragma unroll
            for (int ng = 0; ng < 4; ng++) {
                uint32_t ue[4][2], uo[4][2];
                #pragma unroll
                for (int j = 0; j < 4; j++) {
                    uint4 u = *(const uint4*)(sVl + ((ng*4 + j) * 2 + kp) * 512 + lane * 16);
                    ue[j][0] = u.x; ue[j][1] = u.y; uo[j][0] = u.z; uo[j][1] = u.w;
                }
                #pragma unroll
                for (int j = 0; j < 4; j++) mma_bf16(oacc[ng*4 + j], phe, ue[j]);
                #pragma unroll
                for (int j = 0; j < 4; j++) mma_bf16(oacc[ng*4 + j], pho, uo[j]);
            }
        }
    }

    // ---- Epilogue: reduce l across 4-lane group ONCE, then normalize ----
    #pragma unroll
    for (int off = 1; off <= 2; off <<= 1) {
        l0 += __shfl_xor_sync(0xffffffffu, l0, off, 4);
        l1 += __shfl_xor_sync(0xffffffffu, l1, off, 4);
    }
    const float inv0 = 1.0f / l0;
    const float inv1 = 1.0f / l1;
    const size_t cbase = (size_t)(b * 16 + qt) * NCH;
    #pragma unroll
    for (int n = 0; n < 16; n++) {
        const int c = h * 8 + (n >> 1);
        const size_t off = ((cbase + c) * 8 + w) * 512 + (size_t)(g * 4 + t4) * 16;
        uint32_t uh0, ul0, uh1, ul1;
        split2(oacc[n][0] * inv0, oacc[n][1] * inv0, uh0, ul0);
        split2(oacc[n][2] * inv1, oacc[n][3] * inv1, uh1, ul1);
        const int j0 = (2 * (n & 1)) * 4;
        const int j1 = (1 + 2 * (n & 1)) * 4;
        *(uint32_t*)((char*)acPh + off + j0) = uh0;
        *(uint32_t*)((char*)acPh + off + j1) = uh1;
        *(uint32_t*)((char*)acPl + off + j0) = ul0;
        *(uint32_t*)((char*)acPl + off + j1) = ul1;
    }
}

// ---------------------------------------------------------------------------
// Launch
// ---------------------------------------------------------------------------
extern "C" void kernel_launch(void* const* d_in, const int* in_sizes, int n_in,
                              void* d_out, int out_size)
{
    (void)in_sizes; (void)n_in; (void)out_size;
    const float* query = (const float*)d_in[0];
    const float* key   = (const float*)d_in[1];
    const float* value = (const float*)d_in[2];
    const int*   mask  = (const int*)  d_in[3];
    const float* Wq    = (const float*)d_in[4];
    const float* Wk    = (const float*)d_in[5];
    const float* Wv    = (const float*)d_in[6];
    const float* Wo    = (const float*)d_in[7];
    float* out = (float*)d_out;

    __nv_bfloat16 *aq_h, *aq_l, *ak_h, *ak_l, *av_h, *av_l, *ac_h, *ac_l;
    __nv_bfloat16 *wq_h, *wq_l, *wk_h, *wk_l, *wv_h, *wv_l, *wo_h, *wo_l;
    __nv_bfloat16 *qa_h, *qa_l, *kb_h, *kb_l, *vb_h, *vb_l;
    uint32_t* mb;
    cudaGetSymbolAddress((void**)&aq_h, g_aq_h); cudaGetSymbolAddress((void**)&aq_l, g_aq_l);
    cudaGetSymbolAddress((void**)&ak_h, g_ak_h); cudaGetSymbolAddress((void**)&ak_l, g_ak_l);
    cudaGetSymbolAddress((void**)&av_h, g_av_h); cudaGetSymbolAddress((void**)&av_l, g_av_l);
    cudaGetSymbolAddress((void**)&ac_h, g_ac_h); cudaGetSymbolAddress((void**)&ac_l, g_ac_l);
    cudaGetSymbolAddress((void**)&wq_h, g_wq_h); cudaGetSymbolAddress((void**)&wq_l, g_wq_l);
    cudaGetSymbolAddress((void**)&wk_h, g_wk_h); cudaGetSymbolAddress((void**)&wk_l, g_wk_l);
    cudaGetSymbolAddress((void**)&wv_h, g_wv_h); cudaGetSymbolAddress((void**)&wv_l, g_wv_l);
    cudaGetSymbolAddress((void**)&wo_h, g_wo_h); cudaGetSymbolAddress((void**)&wo_l, g_wo_l);
    cudaGetSymbolAddress((void**)&qa_h, g_qa_h); cudaGetSymbolAddress((void**)&qa_l, g_qa_l);
    cudaGetSymbolAddress((void**)&kb_h, g_kb_h); cudaGetSymbolAddress((void**)&kb_l, g_kb_l);
    cudaGetSymbolAddress((void**)&vb_h, g_vb_h); cudaGetSymbolAddress((void**)&vb_l, g_vb_l);
    cudaGetSymbolAddress((void**)&mb,   g_mb);

    cudaFuncSetAttribute(qkv_gemm, cudaFuncAttributeMaxDynamicSharedMemorySize, GEMM_SMEM);
    cudaFuncSetAttribute(tc_gemm0, cudaFuncAttributeMaxDynamicSharedMemorySize, GEMM_SMEM);
    cudaFuncSetAttribute(gqa_attn_mma, cudaFuncAttributeMaxDynamicSharedMemorySize, ATT_SMEM);

    // Pack mask to bits
    pack_mask<<<(PB * PS * PS) / 256, 256>>>(mask, mb);

    // Pack all four weights in one launch
    pack_w4<<<10240, dim3(32, 8)>>>(Wq, Wk, Wv, Wo,
                                    wq_h, wq_l, wk_h, wk_l, wv_h, wv_l, wo_h, wo_l);

    // Pack all three input activations in one launch
    pack_a3<<<3 * PACKA_BLOCKS_PER, 256>>>(query, key, value,
                                           aq_h, aq_l, ak_h, ak_l, av_h, av_l);

    // Merged Q/K/V projections (V epilogue packs V B-planes directly)
    qkv_gemm<<<dim3(24, PM / 128), 256, GEMM_SMEM>>>(
        aq_h, aq_l, ak_h, ak_l, av_h, av_l,
        wq_h, wq_l, wk_h, wk_l, wv_h, wv_l,
        qa_h, qa_l, kb_h, kb_l, vb_h, vb_l);

    // Tensor-core fused attention (BK=64, no-max softmax) — writes O-proj A-planes
    gqa_attn_mma<<<dim3(PS / 128, PH, PB), 256, ATT_SMEM>>>(
        qa_h, qa_l, kb_h, kb_l, vb_h, vb_l, mb, ac_h, ac_l);

    // Output projection
    tc_gemm0<<<dim3(PD / 128, PM / 128), 256, GEMM_SMEM>>>(
        ac_h, ac_l, wo_h, wo_l, out, PD);
}